// round 6
// baseline (speedup 1.0000x reference)
#include <cuda_runtime.h>
#include <math.h>

// Problem constants
#define BATCH 64
#define CIN 2
#define NN 512
#define TT 12
#define DD 128
#define NROWS (BATCH*CIN*TT)      // 1536 rows per Y level
#define EPSBN 1e-5f

// ---------------- device scratch ----------------
__device__ float g_Y[5 * NROWS * NN];      // y_p, p=0..4, layout [(b*2+e)*12+t][n]
__device__ float g_A2[NN * NN];
__device__ float g_q[5 * NN];              // node basis q_k
__device__ float g_C[2][5 * 256];          // ping-pong: [p][c][e] = p*256 + c*2 + e
__device__ float g_U[2][DD * 5];           // [c][k]
__device__ float g_SkC[5 * 256];
__device__ float g_SkU[DD * 5];
__device__ float g_SkB[NN * DD];           // bias per (n,c)
__device__ float g_Sfin[10 * DD];          // [j=p*2+e][c]

// ---------------- transpose x -> Y0 ----------------
__global__ void k_transpose(const float* __restrict__ x) {
    int idx = blockIdx.x * 256 + threadIdx.x;          // 786432 total
    int row = idx >> 9, n = idx & 511;
    g_Y[idx] = x[(row / TT) * (NN * TT) + n * TT + (row % TT)];
}

// ---------------- SGEMM 128x128x16 core (K=N=512) ----------------
__device__ __forceinline__ void sgemm_core(const float* __restrict__ A,
                                           const float* __restrict__ B,
                                           float* __restrict__ C,
                                           int m0, int n0) {
    __shared__ float As[16][128];
    __shared__ float Bs[16][128];
    const int K = 512, N = 512;
    int tid = threadIdx.x;
    int tx = tid & 15, ty = tid >> 4;
    float acc[8][8];
#pragma unroll
    for (int i = 0; i < 8; i++)
#pragma unroll
        for (int j = 0; j < 8; j++) acc[i][j] = 0.f;

    for (int k0 = 0; k0 < K; k0 += 16) {
#pragma unroll
        for (int l = 0; l < 2; l++) {
            int r = (tid >> 2) + l * 64;
            int c4 = (tid & 3) * 4;
            float4 v = *(const float4*)(A + (size_t)(m0 + r) * K + k0 + c4);
            As[c4 + 0][r] = v.x; As[c4 + 1][r] = v.y;
            As[c4 + 2][r] = v.z; As[c4 + 3][r] = v.w;
        }
#pragma unroll
        for (int l = 0; l < 2; l++) {
            int kr = (tid >> 5) + l * 8;
            int c4 = (tid & 31) * 4;
            *(float4*)&Bs[kr][c4] = *(const float4*)(B + (size_t)(k0 + kr) * N + n0 + c4);
        }
        __syncthreads();
#pragma unroll
        for (int k = 0; k < 16; k++) {
            float a[8], b[8];
            *(float4*)&a[0] = *(const float4*)&As[k][ty * 8];
            *(float4*)&a[4] = *(const float4*)&As[k][ty * 8 + 4];
            *(float4*)&b[0] = *(const float4*)&Bs[k][tx * 8];
            *(float4*)&b[4] = *(const float4*)&Bs[k][tx * 8 + 4];
#pragma unroll
            for (int i = 0; i < 8; i++)
#pragma unroll
                for (int j = 0; j < 8; j++) acc[i][j] += a[i] * b[j];
        }
        __syncthreads();
    }
#pragma unroll
    for (int i = 0; i < 8; i++) {
        int r = m0 + ty * 8 + i;
#pragma unroll
        for (int j4 = 0; j4 < 2; j4++) {
            float4 v = make_float4(acc[i][j4 * 4], acc[i][j4 * 4 + 1],
                                   acc[i][j4 * 4 + 2], acc[i][j4 * 4 + 3]);
            *(float4*)(C + (size_t)r * N + n0 + tx * 8 + j4 * 4) = v;
        }
    }
}

__global__ void k_gemmA2(const float* __restrict__ adj) {          // A2 = A*A  grid(4,4)
    sgemm_core(adj, adj, g_A2, blockIdx.y * 128, blockIdx.x * 128);
}
__global__ void k_hop12(const float* __restrict__ adj) {           // Y1=Y0*A, Y2=Y0*A2  grid(4,12,2)
    const float* B = (blockIdx.z == 0) ? adj : g_A2;
    float* C = (blockIdx.z == 0) ? (g_Y + (size_t)1 * NROWS * NN)
                                 : (g_Y + (size_t)2 * NROWS * NN);
    sgemm_core(g_Y, B, C, blockIdx.y * 128, blockIdx.x * 128);
}
__global__ void k_hop34() {                                        // [Y3;Y4]=[Y1;Y2]*A2  grid(4,24)
    sgemm_core(g_Y + (size_t)1 * NROWS * NN, g_A2, g_Y + (size_t)3 * NROWS * NN,
               blockIdx.y * 128, blockIdx.x * 128);
}

// ---------------- node basis q_k = q_{k-1}^T A ----------------
__global__ void k_qstep(const float* __restrict__ adj, int k) {    // grid 4 x 128
    int w = blockIdx.x * 128 + threadIdx.x;
    const float* qp = g_q + (k - 1) * NN;
    float acc = 0.f;
#pragma unroll 8
    for (int v = 0; v < NN; v++) acc += qp[v] * adj[v * NN + w];
    g_q[k * NN + w] = acc;
}

// ---------------- composite init ----------------
__global__ void k_init(const float* __restrict__ W_start, const float* __restrict__ b_start) {
    int tid = threadIdx.x;                                         // 512 threads, 1 block
    for (int i = tid; i < 1280; i += 512) { g_C[0][i] = 0.f; g_SkC[i] = 0.f; }
    for (int i = tid; i < 640;  i += 512) { g_U[0][i] = 0.f; g_SkU[i] = 0.f; }
    if (tid < 512) g_q[tid] = 1.0f;
    __syncthreads();
    if (tid < 256) g_C[0][tid] = W_start[tid];                     // p=0 block, [c*2+e]
    if (tid < 128) g_U[0][tid * 5] = b_start[tid];                 // k=0
}

// ---------------- skip accumulation ----------------
__global__ void k_skip(const float* __restrict__ W_skip, const float* __restrict__ b_skip,
                       int i, int cur) {                           // grid 15 x 128
    __shared__ float vec[128];
    int bc = blockIdx.x, c = threadIdx.x;
    const float* Wr = W_skip + i * (DD * DD) + c * DD;
    if (bc < 10) {
        int p = bc >> 1, e = bc & 1;
        vec[c] = g_C[cur][p * 256 + c * 2 + e];
        __syncthreads();
        float acc = 0.f;
#pragma unroll 8
        for (int m = 0; m < DD; m++) acc += Wr[m] * vec[m];
        g_SkC[p * 256 + c * 2 + e] += acc;
    } else {
        int k = bc - 10;
        vec[c] = g_U[cur][c * 5 + k];
        __syncthreads();
        float acc = (k == 0) ? b_skip[i * DD + c] : 0.f;
#pragma unroll 8
        for (int m = 0; m < DD; m++) acc += Wr[m] * vec[m];
        g_SkU[c * 5 + k] += acc;
    }
}

// ---------------- one graph-conv + BN + residual + BN step ----------------
__global__ void k_gc(const float* __restrict__ W_gc, const float* __restrict__ b_gc,
                     const float* __restrict__ gcg, const float* __restrict__ gcb,
                     const float* __restrict__ gcm, const float* __restrict__ gcv,
                     const float* __restrict__ bng, const float* __restrict__ bnb,
                     const float* __restrict__ bnm, const float* __restrict__ bnv,
                     int i, int cur) {                             // grid 15 x 128
    __shared__ float vec[384];
    int nxt = cur ^ 1;
    int bc = blockIdx.x, c = threadIdx.x;
    const float* Wr = W_gc + i * (DD * 3 * DD) + c * (3 * DD);
    float ig = gcg[i * DD + c] * rsqrtf(gcv[i * DD + c] + EPSBN);
    float mg = gcb[i * DD + c] - gcm[i * DD + c] * ig;
    float ib = bng[i * DD + c] * rsqrtf(bnv[i * DD + c] + EPSBN);
    float mb = bnb[i * DD + c] - bnm[i * DD + c] * ib;
    if (bc < 10) {
        int p = bc >> 1, e = bc & 1;
        vec[c]       = g_C[cur][p * 256 + c * 2 + e];
        vec[128 + c] = (p >= 1) ? g_C[cur][(p - 1) * 256 + c * 2 + e] : 0.f;
        vec[256 + c] = (p >= 2) ? g_C[cur][(p - 2) * 256 + c * 2 + e] : 0.f;
        __syncthreads();
        float h = 0.f;
#pragma unroll 8
        for (int j = 0; j < 384; j++) h += Wr[j] * vec[j];
        float oldv = vec[c];
        g_C[nxt][p * 256 + c * 2 + e] = ib * (ig * h + oldv);
    } else {
        int k = bc - 10;
        vec[c]       = g_U[cur][c * 5 + k];
        vec[128 + c] = (k >= 1) ? g_U[cur][c * 5 + k - 1] : 0.f;
        vec[256 + c] = (k >= 2) ? g_U[cur][c * 5 + k - 2] : 0.f;
        __syncthreads();
        float h = 0.f;
#pragma unroll 8
        for (int j = 0; j < 384; j++) h += Wr[j] * vec[j];
        if (k == 0) h += b_gc[i * DD + c];
        float oldv = vec[c];
        float val = ib * (ig * h + ((k == 0) ? mg : 0.f) + oldv) + ((k == 0) ? mb : 0.f);
        g_U[nxt][c * 5 + k] = val;
    }
}

// ---------------- finalize bias field & output matrices ----------------
__global__ void k_skb(const float* __restrict__ obg, const float* __restrict__ obb,
                      const float* __restrict__ obm, const float* __restrict__ obv) {
    int idx = blockIdx.x * 256 + threadIdx.x;                      // grid 256 x 256 = 65536
    int n = idx >> 7, c = idx & 127;
    float io = obg[c] * rsqrtf(obv[c] + EPSBN);
    float mo = obb[c] - obm[c] * io;
    float acc = 0.f;
#pragma unroll
    for (int k = 0; k < 5; k++) acc += g_SkU[c * 5 + k] * g_q[k * NN + n];
    g_SkB[n * DD + c] = io * acc + mo;
    if (blockIdx.x == 0) {
        for (int jj = threadIdx.x; jj < 1280; jj += 256) {
            int j = jj >> 7, cc = jj & 127;
            int p = j >> 1, e = j & 1;
            float io2 = obg[cc] * rsqrtf(obv[cc] + EPSBN);
            g_Sfin[j * DD + cc] = io2 * g_SkC[p * 256 + cc * 2 + e];
        }
    }
}

// ---------------- final output: out[b,t,n,c] = sum_j Sfin[j][c]*y_j + SkB[n][c] ----------------
__global__ void k_final(float* __restrict__ out) {                 // grid(16,12,64) x 256
    __shared__ float yv[10][32];
    __shared__ float S[10][128];
    int n0 = blockIdx.x * 32, t = blockIdx.y, b = blockIdx.z;
    int tid = threadIdx.x;
    for (int s = tid; s < 320; s += 256) {
        int j = s >> 5, ii = s & 31;
        int p = j >> 1, e = j & 1;
        yv[j][ii] = g_Y[((size_t)p * NROWS + (b * 2 + e) * TT + t) * NN + n0 + ii];
    }
    for (int s = tid; s < 1280; s += 256) S[s >> 7][s & 127] = g_Sfin[s];
    __syncthreads();
    int i = tid >> 3, c0 = (tid & 7) * 16;
    float acc[16];
    const float* bb = g_SkB + (n0 + i) * DD + c0;
#pragma unroll
    for (int cc = 0; cc < 16; cc++) acc[cc] = bb[cc];
#pragma unroll
    for (int j = 0; j < 10; j++) {
        float yj = yv[j][i];
#pragma unroll
        for (int cc = 0; cc < 16; cc++) acc[cc] += yj * S[j][c0 + cc];
    }
    float* op = out + (((size_t)(b * TT + t) * NN) + n0 + i) * DD + c0;
#pragma unroll
    for (int q4 = 0; q4 < 4; q4++)
        *(float4*)(op + q4 * 4) = make_float4(acc[q4 * 4], acc[q4 * 4 + 1],
                                              acc[q4 * 4 + 2], acc[q4 * 4 + 3]);
}

// ---------------- launcher ----------------
extern "C" void kernel_launch(void* const* d_in, const int* in_sizes, int n_in,
                              void* d_out, int out_size) {
    const float* x       = (const float*)d_in[0];
    const float* adj     = (const float*)d_in[1];
    const float* W_start = (const float*)d_in[2];
    const float* b_start = (const float*)d_in[3];
    const float* W_skip  = (const float*)d_in[4];
    const float* b_skip  = (const float*)d_in[5];
    const float* W_gc    = (const float*)d_in[6];
    const float* b_gc    = (const float*)d_in[7];
    const float* gcg     = (const float*)d_in[8];
    const float* gcb     = (const float*)d_in[9];
    const float* gcm     = (const float*)d_in[10];
    const float* gcv     = (const float*)d_in[11];
    const float* bng     = (const float*)d_in[12];
    const float* bnb     = (const float*)d_in[13];
    const float* bnm     = (const float*)d_in[14];
    const float* bnv     = (const float*)d_in[15];
    const float* obg     = (const float*)d_in[16];
    const float* obb     = (const float*)d_in[17];
    const float* obm     = (const float*)d_in[18];
    const float* obv     = (const float*)d_in[19];
    float* out = (float*)d_out;

    // data path: Y0, A2, hops
    k_transpose<<<3072, 256>>>(x);
    k_gemmA2<<<dim3(4, 4), 256>>>(adj);
    k_hop12<<<dim3(4, 12, 2), 256>>>(adj);
    k_hop34<<<dim3(4, 24), 256>>>();

    // composite path (tiny)
    k_init<<<1, 512>>>(W_start, b_start);
    k_qstep<<<4, 128>>>(adj, 1);
    k_qstep<<<4, 128>>>(adj, 2);
    k_qstep<<<4, 128>>>(adj, 3);
    k_qstep<<<4, 128>>>(adj, 4);

    k_skip<<<15, 128>>>(W_skip, b_skip, 0, 0);
    k_gc<<<15, 128>>>(W_gc, b_gc, gcg, gcb, gcm, gcv, bng, bnb, bnm, bnv, 0, 0);
    k_skip<<<15, 128>>>(W_skip, b_skip, 1, 1);
    k_gc<<<15, 128>>>(W_gc, b_gc, gcg, gcb, gcm, gcv, bng, bnb, bnm, bnv, 1, 1);
    k_skip<<<15, 128>>>(W_skip, b_skip, 2, 0);

    k_skb<<<256, 256>>>(obg, obb, obm, obv);

    // output expansion (DRAM-bound)
    k_final<<<dim3(16, 12, 64), 256>>>(out);
    (void)in_sizes; (void)n_in; (void)out_size;
}

// round 9
// speedup vs baseline: 1.0329x; 1.0329x over previous
#include <cuda_runtime.h>
#include <math.h>

#define NNODE 512
#define TT 12
#define DD 128
#define NROWS 1536            // 64*2*12 rows per Y level
#define EPSBN 1e-5f

// ---------------- device scratch ----------------
__device__ float g_Y[5 * NROWS * NNODE];   // y_p, p=0..4, rows=(b*2+e)*12+t
__device__ float g_A2[NNODE * NNODE];
__device__ float g_q[5 * NNODE];           // rows 1..4 used
__device__ float g_Sfin[10 * DD];          // [j=p*2+e][c]
__device__ float g_SkUf[DD * 5];           // [c][k], ob-scaled
__device__ float g_mo[DD];

// ---------------- transpose x -> Y0 (smem transpose, coalesced both ways) ----
__global__ void k_transpose(const float* __restrict__ x) {   // grid 128, 256 thr
    __shared__ float s[NNODE * TT];
    int bc = blockIdx.x, tid = threadIdx.x;
    const float* src = x + (size_t)bc * (NNODE * TT);
    for (int i = tid; i < NNODE * TT; i += 256) s[i] = src[i];   // s[n*12+t]
    __syncthreads();
    float* dst = g_Y + (size_t)bc * TT * NNODE;
    for (int i = tid; i < NNODE * TT; i += 256) {
        int t = i >> 9, n = i & 511;
        dst[i] = s[n * TT + t];
    }
}

// ---------------- 64x64 double-buffered SGEMM core (K = N = 512) -------------
__device__ __forceinline__ void sgemm64(const float* __restrict__ A,
                                        const float* __restrict__ B,
                                        float* __restrict__ C,
                                        int m0, int n0) {
    __shared__ float As[2][16][64];
    __shared__ float Bs[2][16][64];
    int tid = threadIdx.x;
    int tx = tid & 15, ty = tid >> 4;          // tx: n/4, ty: m/4
    int ar = tid >> 2, ak = (tid & 3) << 2;    // A tile load: row, k-col
    int bk = tid >> 4, bc = (tid & 15) << 2;   // B tile load: k-row, col
    const float* Ap = A + (size_t)(m0 + ar) * 512 + ak;
    const float* Bp = B + (size_t)bk * 512 + n0 + bc;

    float4 av = *(const float4*)Ap;
    float4 bv = *(const float4*)Bp;
    As[0][ak + 0][ar] = av.x; As[0][ak + 1][ar] = av.y;
    As[0][ak + 2][ar] = av.z; As[0][ak + 3][ar] = av.w;
    *(float4*)&Bs[0][bk][bc] = bv;
    __syncthreads();

    float acc[4][4] = {};
#pragma unroll 1
    for (int kt = 0; kt < 32; kt++) {
        int cur = kt & 1;
        if (kt < 31) {
            av = *(const float4*)(Ap + (kt + 1) * 16);
            bv = *(const float4*)(Bp + (size_t)(kt + 1) * 16 * 512);
        }
#pragma unroll
        for (int k = 0; k < 16; k++) {
            float a[4], b[4];
            *(float4*)a = *(const float4*)&As[cur][k][ty * 4];
            *(float4*)b = *(const float4*)&Bs[cur][k][tx * 4];
#pragma unroll
            for (int i = 0; i < 4; i++)
#pragma unroll
                for (int j = 0; j < 4; j++) acc[i][j] += a[i] * b[j];
        }
        if (kt < 31) {
            int nx = cur ^ 1;
            As[nx][ak + 0][ar] = av.x; As[nx][ak + 1][ar] = av.y;
            As[nx][ak + 2][ar] = av.z; As[nx][ak + 3][ar] = av.w;
            *(float4*)&Bs[nx][bk][bc] = bv;
            __syncthreads();
        }
    }
#pragma unroll
    for (int i = 0; i < 4; i++) {
        float4 v = make_float4(acc[i][0], acc[i][1], acc[i][2], acc[i][3]);
        *(float4*)(C + (size_t)(m0 + ty * 4 + i) * 512 + n0 + tx * 4) = v;
    }
}

__global__ void __launch_bounds__(256) k_gemmA2(const float* __restrict__ adj) {
    sgemm64(adj, adj, g_A2, blockIdx.y * 64, blockIdx.x * 64);    // grid(8,8)
}
__global__ void __launch_bounds__(256) k_hop12(const float* __restrict__ adj) {
    const float* B = (blockIdx.z == 0) ? adj : g_A2;              // grid(8,24,2)
    float* C = g_Y + (size_t)(1 + blockIdx.z) * NROWS * NNODE;
    sgemm64(g_Y, B, C, blockIdx.y * 64, blockIdx.x * 64);
}
__global__ void __launch_bounds__(256) k_hop34() {                // grid(8,48)
    sgemm64(g_Y + (size_t)1 * NROWS * NNODE, g_A2,
            g_Y + (size_t)3 * NROWS * NNODE, blockIdx.y * 64, blockIdx.x * 64);
}

// ---------------- node basis: q1=1'A, q2=1'A2, then q3=q1'A2, q4=q2'A2 -------
__global__ void k_q12(const float* __restrict__ adj) {            // grid 8, 128 thr
    int bid = blockIdx.x;
    const float* M = (bid < 4) ? adj : g_A2;
    int w = (bid & 3) * 128 + threadIdx.x;
    float acc = 0.f;
#pragma unroll 8
    for (int v = 0; v < 512; v++) acc += M[v * 512 + w];
    g_q[(bid < 4 ? 1 : 2) * NNODE + w] = acc;
}
__global__ void k_q34() {                                         // grid 8, 128 thr
    __shared__ float qs[512];
    int bid = blockIdx.x;
    int src = (bid < 4) ? 1 : 2;
    for (int i = threadIdx.x; i < 512; i += 128) qs[i] = g_q[src * NNODE + i];
    __syncthreads();
    int w = (bid & 3) * 128 + threadIdx.x;
    float acc = 0.f;
#pragma unroll 8
    for (int v = 0; v < 512; v++) acc += qs[v] * g_A2[v * 512 + w];
    g_q[(src + 2) * NNODE + w] = acc;
}

// ---------------- fused composite chain: init + 3 skip + 2 gc + finalize -----
__global__ void __launch_bounds__(128) k_composite(
    const float* __restrict__ W_start, const float* __restrict__ b_start,
    const float* __restrict__ W_skip,  const float* __restrict__ b_skip,
    const float* __restrict__ W_gc,    const float* __restrict__ b_gc,
    const float* __restrict__ gcg, const float* __restrict__ gcb,
    const float* __restrict__ gcm, const float* __restrict__ gcv,
    const float* __restrict__ bng, const float* __restrict__ bnb,
    const float* __restrict__ bnm, const float* __restrict__ bnv,
    const float* __restrict__ obg, const float* __restrict__ obb,
    const float* __restrict__ obm, const float* __restrict__ obv)
{
    __shared__ float Sg[6144];          // staging [j][16], 15 vecs used
    __shared__ float Ca[2][1280];       // C composites [p*256 + m*2 + e]
    __shared__ float Ua[2][640];        // U composites [m*5 + k]
    __shared__ float SkC[1280];
    __shared__ float SkU[640];
    int c = threadIdx.x;

    for (int i2 = c; i2 < 1280; i2 += 128) { Ca[0][i2] = 0.f; SkC[i2] = 0.f; }
    for (int i2 = c; i2 < 640;  i2 += 128) { Ua[0][i2] = 0.f; SkU[i2] = 0.f; }
    __syncthreads();
    Ca[0][c * 2 + 0] = W_start[c * 2 + 0];
    Ca[0][c * 2 + 1] = W_start[c * 2 + 1];
    Ua[0][c * 5] = b_start[c];
    __syncthreads();

    int cur = 0;
    for (int s = 0; s < 5; s++) {
        int i = s >> 1;
        if ((s & 1) == 0) {
            // ---- skip step i: SkC/SkU += W_skip[i] * composites ----
            for (int idx = c; idx < 2048; idx += 128) {
                int m = idx >> 4, v = idx & 15; float val = 0.f;
                if (v < 10) val = Ca[cur][(v >> 1) * 256 + m * 2 + (v & 1)];
                else if (v < 15) val = Ua[cur][m * 5 + (v - 10)];
                Sg[idx] = val;
            }
            __syncthreads();
            float acc[15];
#pragma unroll
            for (int v = 0; v < 15; v++) acc[v] = 0.f;
            const float* Wr = W_skip + i * (DD * DD) + c * DD;
#pragma unroll 4
            for (int m = 0; m < 128; m++) {
                float w = Wr[m];
                float4 s0 = *(const float4*)&Sg[m * 16 + 0];
                float4 s1 = *(const float4*)&Sg[m * 16 + 4];
                float4 s2 = *(const float4*)&Sg[m * 16 + 8];
                float4 s3 = *(const float4*)&Sg[m * 16 + 12];
                acc[0] += w * s0.x; acc[1] += w * s0.y; acc[2] += w * s0.z; acc[3] += w * s0.w;
                acc[4] += w * s1.x; acc[5] += w * s1.y; acc[6] += w * s1.z; acc[7] += w * s1.w;
                acc[8] += w * s2.x; acc[9] += w * s2.y; acc[10] += w * s2.z; acc[11] += w * s2.w;
                acc[12] += w * s3.x; acc[13] += w * s3.y; acc[14] += w * s3.z;
            }
#pragma unroll
            for (int v = 0; v < 10; v++)
                SkC[(v >> 1) * 256 + c * 2 + (v & 1)] += acc[v];
#pragma unroll
            for (int k = 0; k < 5; k++)
                SkU[c * 5 + k] += acc[10 + k] + ((k == 0) ? b_skip[i * DD + c] : 0.f);
            __syncthreads();
        } else {
            // ---- gc step i: [x, Ax, A2x] -> conv -> BN -> +res -> BN ----
            for (int idx = c; idx < 6144; idx += 128) {
                int j = idx >> 4, v = idx & 15;
                int sub = j >> 7, m = j & 127;
                float val = 0.f;
                if (v < 10) { int p = (v >> 1) - sub;
                              if (p >= 0) val = Ca[cur][p * 256 + m * 2 + (v & 1)]; }
                else if (v < 15) { int k = (v - 10) - sub;
                                   if (k >= 0) val = Ua[cur][m * 5 + k]; }
                Sg[idx] = val;
            }
            __syncthreads();
            float acc[15];
#pragma unroll
            for (int v = 0; v < 15; v++) acc[v] = 0.f;
            const float* Wr = W_gc + i * (DD * 3 * DD) + c * (3 * DD);
#pragma unroll 4
            for (int j = 0; j < 384; j++) {
                float w = Wr[j];
                float4 s0 = *(const float4*)&Sg[j * 16 + 0];
                float4 s1 = *(const float4*)&Sg[j * 16 + 4];
                float4 s2 = *(const float4*)&Sg[j * 16 + 8];
                float4 s3 = *(const float4*)&Sg[j * 16 + 12];
                acc[0] += w * s0.x; acc[1] += w * s0.y; acc[2] += w * s0.z; acc[3] += w * s0.w;
                acc[4] += w * s1.x; acc[5] += w * s1.y; acc[6] += w * s1.z; acc[7] += w * s1.w;
                acc[8] += w * s2.x; acc[9] += w * s2.y; acc[10] += w * s2.z; acc[11] += w * s2.w;
                acc[12] += w * s3.x; acc[13] += w * s3.y; acc[14] += w * s3.z;
            }
            float ig = gcg[i * DD + c] * rsqrtf(gcv[i * DD + c] + EPSBN);
            float mg = gcb[i * DD + c] - gcm[i * DD + c] * ig;
            float ib = bng[i * DD + c] * rsqrtf(bnv[i * DD + c] + EPSBN);
            float mb = bnb[i * DD + c] - bnm[i * DD + c] * ib;
            int nx = cur ^ 1;
#pragma unroll
            for (int v = 0; v < 10; v++) {
                int p = v >> 1, e = v & 1;
                Ca[nx][p * 256 + c * 2 + e] =
                    ib * (ig * acc[v] + Ca[cur][p * 256 + c * 2 + e]);
            }
#pragma unroll
            for (int k = 0; k < 5; k++) {
                float h = acc[10 + k] + ((k == 0) ? b_gc[i * DD + c] : 0.f);
                Ua[nx][c * 5 + k] = ib * (ig * h + ((k == 0) ? mg : 0.f)
                                          + Ua[cur][c * 5 + k]) + ((k == 0) ? mb : 0.f);
            }
            cur = nx;
            __syncthreads();
        }
    }
    // finalize with output BN folded in
    float io = obg[c] * rsqrtf(obv[c] + EPSBN);
    float mo = obb[c] - obm[c] * io;
#pragma unroll
    for (int v = 0; v < 10; v++)
        g_Sfin[v * DD + c] = io * SkC[(v >> 1) * 256 + c * 2 + (v & 1)];
#pragma unroll
    for (int k = 0; k < 5; k++)
        g_SkUf[c * 5 + k] = io * SkU[c * 5 + k];
    g_mo[c] = mo;
}

// ---------------- final: out[b,t,n,c] = sum_j Sfin[j][c]*y_j + bias(n,c) -----
__global__ void __launch_bounds__(256) k_final(float* __restrict__ out) {
    __shared__ float yv[10][32];
    __shared__ float S[10][128];
    __shared__ float qv[4][32];
    __shared__ float SkUs[DD * 5];
    __shared__ float mos[DD];
    int n0 = blockIdx.x * 32, t = blockIdx.y, b = blockIdx.z;
    int tid = threadIdx.x;
    for (int s = tid; s < 320; s += 256) {
        int j = s >> 5, ii = s & 31;
        int p = j >> 1, e = j & 1;
        yv[j][ii] = g_Y[((size_t)p * NROWS + (b * 2 + e) * TT + t) * NNODE + n0 + ii];
    }
    for (int s = tid; s < 1280; s += 256) S[s >> 7][s & 127] = g_Sfin[s];
    for (int s = tid; s < 640; s += 256) SkUs[s] = g_SkUf[s];
    if (tid < 128) {
        qv[tid >> 5][tid & 31] = g_q[((tid >> 5) + 1) * NNODE + n0 + (tid & 31)];
        mos[tid] = g_mo[tid];
    }
    __syncthreads();
    int i = tid >> 3, c0 = (tid & 7) * 16;
    float q1 = qv[0][i], q2 = qv[1][i], q3 = qv[2][i], q4 = qv[3][i];
    float acc[16];
#pragma unroll
    for (int cc = 0; cc < 16; cc++) {
        int cch = c0 + cc;
        acc[cc] = mos[cch] + SkUs[cch * 5 + 0] + SkUs[cch * 5 + 1] * q1
                + SkUs[cch * 5 + 2] * q2 + SkUs[cch * 5 + 3] * q3
                + SkUs[cch * 5 + 4] * q4;
    }
#pragma unroll
    for (int j = 0; j < 10; j++) {
        float yj = yv[j][i];
#pragma unroll
        for (int cc = 0; cc < 16; cc++) acc[cc] += yj * S[j][c0 + cc];
    }
    float* op = out + (((size_t)(b * TT + t) * NNODE) + n0 + i) * DD + c0;
#pragma unroll
    for (int q4i = 0; q4i < 4; q4i++)
        *(float4*)(op + q4i * 4) = make_float4(acc[q4i * 4], acc[q4i * 4 + 1],
                                               acc[q4i * 4 + 2], acc[q4i * 4 + 3]);
}

// ---------------- launcher ----------------
extern "C" void kernel_launch(void* const* d_in, const int* in_sizes, int n_in,
                              void* d_out, int out_size) {
    const float* x       = (const float*)d_in[0];
    const float* adj     = (const float*)d_in[1];
    const float* W_start = (const float*)d_in[2];
    const float* b_start = (const float*)d_in[3];
    const float* W_skip  = (const float*)d_in[4];
    const float* b_skip  = (const float*)d_in[5];
    const float* W_gc    = (const float*)d_in[6];
    const float* b_gc    = (const float*)d_in[7];
    const float* gcg     = (const float*)d_in[8];
    const float* gcb     = (const float*)d_in[9];
    const float* gcm     = (const float*)d_in[10];
    const float* gcv     = (const float*)d_in[11];
    const float* bng     = (const float*)d_in[12];
    const float* bnb     = (const float*)d_in[13];
    const float* bnm     = (const float*)d_in[14];
    const float* bnv     = (const float*)d_in[15];
    const float* obg     = (const float*)d_in[16];
    const float* obb     = (const float*)d_in[17];
    const float* obm     = (const float*)d_in[18];
    const float* obv     = (const float*)d_in[19];
    float* out = (float*)d_out;

    k_transpose<<<128, 256>>>(x);
    k_gemmA2<<<dim3(8, 8), 256>>>(adj);
    k_hop12<<<dim3(8, 24, 2), 256>>>(adj);
    k_hop34<<<dim3(8, 48), 256>>>();
    k_q12<<<8, 128>>>(adj);
    k_q34<<<8, 128>>>();
    k_composite<<<1, 128>>>(W_start, b_start, W_skip, b_skip, W_gc, b_gc,
                            gcg, gcb, gcm, gcv, bng, bnb, bnm, bnv,
                            obg, obb, obm, obv);
    k_final<<<dim3(16, 12, 64), 256>>>(out);
    (void)in_sizes; (void)n_in; (void)out_size;
}